// round 5
// baseline (speedup 1.0000x reference)
#include <cuda_runtime.h>
#include <cuda_bf16.h>

typedef unsigned long long u64;

// Problem dims
#define T_DIM 512
#define B_DIM 32
#define I_DIM 512
#define H_DIM 512
#define G_DIM 2048                       // 4*H
#define S_TBH (T_DIM*B_DIM*H_DIM)        // one [T,B,H] slab
#define NCTA 128

// Scratch: pre-activations for one layer [T, B, 4H]
__device__ float g_pre[(size_t)T_DIM * B_DIM * G_DIM];

// Entry grid-barrier state (monotonic across graph replays)
__device__ unsigned gSub[8 * 32];
__device__ unsigned gMaster;
__device__ unsigned gGen;
// Per-CTA dataflow step counters (reset each launch after entry barrier)
__device__ unsigned gStep[NCTA * 32];    // one 128B line per CTA

// ---- f32x2 helpers ---------------------------------------------------------
__device__ __forceinline__ u64 ffma2(u64 a, u64 b, u64 c) {
    u64 d; asm("fma.rn.f32x2 %0,%1,%2,%3;" : "=l"(d) : "l"(a), "l"(b), "l"(c));
    return d;
}
__device__ __forceinline__ u64 fsplat(float a) {
    u64 r; asm("mov.b64 %0,{%1,%1};" : "=l"(r) : "f"(a)); return r;
}
__device__ __forceinline__ float2 funpack(u64 v) {
    float lo, hi; asm("mov.b64 {%0,%1},%2;" : "=f"(lo), "=f"(hi) : "l"(v));
    return make_float2(lo, hi);
}
// ---- acquire/release helpers ----------------------------------------------
__device__ __forceinline__ unsigned ld_acq(const unsigned* p) {
    unsigned v;
    asm volatile("ld.acquire.gpu.global.u32 %0,[%1];" : "=r"(v) : "l"(p));
    return v;
}
__device__ __forceinline__ void red_add_rel(unsigned* p, unsigned v) {
    asm volatile("red.release.gpu.global.add.u32 [%0],%1;" :: "l"(p), "r"(v));
}
__device__ __forceinline__ float sigf(float x) {
    return 1.f / (1.f + __expf(-x));
}

// ---------------------------------------------------------------------------
// GEMM: pre[M,N] = A[M,K] @ W[N,K]^T + bih[N] + bhh[N]   (unchanged, works)
// ---------------------------------------------------------------------------
__global__ __launch_bounds__(256) void gemm_pre_kernel(
    const float* __restrict__ A,
    const float* __restrict__ W,
    const float* __restrict__ bih,
    const float* __restrict__ bhh,
    float* __restrict__ C)
{
    const int K = I_DIM;
    const int N = G_DIM;

    __shared__ float As[2][8][128];
    __shared__ float Bs[2][8][128];

    const int bm = blockIdx.y * 128;
    const int bn = blockIdx.x * 128;
    const int tid = threadIdx.x;
    const int tx = tid & 15;
    const int ty = tid >> 4;

    u64 acc2[8][4];
#pragma unroll
    for (int i = 0; i < 8; i++)
#pragma unroll
        for (int jp = 0; jp < 4; jp++) acc2[i][jp] = 0ull;

    const int lr = tid >> 1;
    const int lc = (tid & 1) * 4;
    const float* Aptr = A + (size_t)(bm + lr) * K + lc;
    const float* Wptr = W + (size_t)(bn + lr) * K + lc;

    float4 av = *(const float4*)(Aptr);
    float4 wv = *(const float4*)(Wptr);
    As[0][lc + 0][lr] = av.x; As[0][lc + 1][lr] = av.y;
    As[0][lc + 2][lr] = av.z; As[0][lc + 3][lr] = av.w;
    Bs[0][lc + 0][lr] = wv.x; Bs[0][lc + 1][lr] = wv.y;
    Bs[0][lc + 2][lr] = wv.z; Bs[0][lc + 3][lr] = wv.w;
    __syncthreads();

    for (int kt = 0; kt < 64; kt++) {
        const int cur = kt & 1;
        if (kt < 63) {
            av = *(const float4*)(Aptr + (kt + 1) * 8);
            wv = *(const float4*)(Wptr + (kt + 1) * 8);
        }
#pragma unroll
        for (int kk = 0; kk < 8; kk++) {
            float a[8];
            *(float4*)(a)     = *(const float4*)&As[cur][kk][ty * 8];
            *(float4*)(a + 4) = *(const float4*)&As[cur][kk][ty * 8 + 4];
            const ulonglong2* bp = (const ulonglong2*)&Bs[cur][kk][tx * 8];
            ulonglong2 q0 = bp[0], q1 = bp[1];
            u64 b2[4] = { q0.x, q0.y, q1.x, q1.y };
#pragma unroll
            for (int i = 0; i < 8; i++) {
                u64 a2 = fsplat(a[i]);
#pragma unroll
                for (int jp = 0; jp < 4; jp++)
                    acc2[i][jp] = ffma2(a2, b2[jp], acc2[i][jp]);
            }
        }
        if (kt < 63) {
            const int nxt = cur ^ 1;
            As[nxt][lc + 0][lr] = av.x; As[nxt][lc + 1][lr] = av.y;
            As[nxt][lc + 2][lr] = av.z; As[nxt][lc + 3][lr] = av.w;
            Bs[nxt][lc + 0][lr] = wv.x; Bs[nxt][lc + 1][lr] = wv.y;
            Bs[nxt][lc + 2][lr] = wv.z; Bs[nxt][lc + 3][lr] = wv.w;
        }
        __syncthreads();
    }

    float bias[8];
#pragma unroll
    for (int j = 0; j < 8; j++) {
        int col = bn + tx * 8 + j;
        bias[j] = bih[col] + bhh[col];
    }
#pragma unroll
    for (int i = 0; i < 8; i++) {
        int row = bm + ty * 8 + i;
        float* cp = C + (size_t)row * N + bn + tx * 8;
        float o[8];
#pragma unroll
        for (int jp = 0; jp < 4; jp++) {
            float2 v = funpack(acc2[i][jp]);
            o[2 * jp]     = v.x + bias[2 * jp];
            o[2 * jp + 1] = v.y + bias[2 * jp + 1];
        }
        *(float4*)(cp)     = make_float4(o[0], o[1], o[2], o[3]);
        *(float4*)(cp + 4) = make_float4(o[4], o[5], o[6], o[7]);
    }
}

// ---------------------------------------------------------------------------
// Persistent LSTM recurrence, dataflow-synchronized (no per-step grid barrier).
// 128 CTAs x 512 threads. CTA bx owns units j0=4*bx..+3 (16 gate cols).
// Warp kq computes all 16 cols over k-slice [32*kq, 32*kq+32):
//   - waits (acquire) on its 2 producer CTAs' step counters
//   - LDGs its h slice [32 b x 32 k] directly into registers
//   - FFMA2 with W transposed [k][c] from smem (broadcast reads)
// One __syncthreads per step; partials double-buffered by parity.
// Pointwise: 128 threads as (b, gate): float4 reduce over 16 warps,
// + pre[t] (prefetched), activations, warp-local exchange, c/h update,
// release-increment of own counter (4 arrivals per step).
// ---------------------------------------------------------------------------
__global__ __launch_bounds__(512, 1) void lstm_recur_kernel(
    const float* __restrict__ pre,     // [T, B, 4H]
    const float* __restrict__ whh,     // [4H, H]
    float* __restrict__ out,           // [6, L, T, B, H]
    int layer)
{
    extern __shared__ float smf[];
    float* sWT  = smf;                 // [512][16] transposed W  (8192 f)
    float* sg   = smf + 8192;          // [2][16][32][20] partials (20480 f)
    float* sAct = sg + 20480;          // [4 warps][8b][4g][4]     (512 f)
    float* sc   = sAct + 512;          // [128] c state
    __shared__ unsigned base_s;

    const int tid = threadIdx.x;
    const int bx  = blockIdx.x;
    const int j0  = bx * 4;

    float* out_h = out + (size_t)layer * S_TBH;
    float* out_c = out + (size_t)1 * 2 * S_TBH + (size_t)layer * S_TBH;

    // ---- load W transposed: sWT[k*16 + c] = whh[gate*512+j0+jl][k]
    const float4* whh4 = (const float4*)whh;
#pragma unroll
    for (int i = 0; i < 4; i++) {
        int idx = tid + i * 512;            // 0..2047
        int c = idx >> 7, k4 = idx & 127;
        int row = (c >> 2) * 512 + j0 + (c & 3);
        float4 v = whh4[(size_t)row * 128 + k4];
        sWT[(4 * k4 + 0) * 16 + c] = v.x;
        sWT[(4 * k4 + 1) * 16 + c] = v.y;
        sWT[(4 * k4 + 2) * 16 + c] = v.z;
        sWT[(4 * k4 + 3) * 16 + c] = v.w;
    }
    if (tid < 128) sc[tid] = 0.f;

    // ---- reset own counter, then one entry grid barrier (monotonic gGen)
    if (tid == 0) {
        *(volatile unsigned*)&gStep[bx * 32] = 0u;
        base_s = *(volatile unsigned*)&gGen;   // safe: gGen can't advance
    }                                          // until all CTAs arrive below
    __syncthreads();
    if (tid == 0) {
        __threadfence();
        unsigned v = atomicAdd(&gSub[(bx & 7) * 32], 1u) + 1u;
        if ((v & 15u) == 0u) {
            unsigned m = atomicAdd(&gMaster, 1u) + 1u;
            if ((m & 7u) == 0u) atomicAdd(&gGen, 1u);
        }
        unsigned target = base_s + 1u;
        while ((int)(*(volatile unsigned*)&gGen - target) < 0) {}
        __threadfence();
    }
    __syncthreads();

    const int kq   = tid >> 5;          // warp = k-slice 0..15
    const int lane = tid & 31;          // lane = batch b
    // pointwise role (tid < 128): (b = w4*8 + l>>2, g = l&3)
    const int w4 = tid >> 5;            // 0..3 when tid<128
    const int pl = tid & 31;
    const int pb = w4 * 8 + (pl >> 2);
    const int pg = pl & 3;
    float* outq = out + (size_t)(2 + pg) * 2 * S_TBH + (size_t)layer * S_TBH;

    for (int t = 0; t < T_DIM; t++) {
        const int par = t & 1;

        // prefetch pre[t] for pointwise (hidden under compute)
        float4 pre4;
        if (tid < 128)
            pre4 = *(const float4*)(pre + (size_t)t * (B_DIM * G_DIM)
                                    + pb * G_DIM + pg * 512 + j0);

        u64 acc[8];
#pragma unroll
        for (int c = 0; c < 8; c++) acc[c] = 0ull;

        if (t > 0) {
            // wait for the 2 producers of this warp's h slice
            unsigned need = 4u * (unsigned)t;
            if (lane < 2) {
                const unsigned* ctr = &gStep[(2 * kq + lane) * 32];
                while (ld_acq(ctr) < need) {}
            }
            __syncwarp();

            // load h slice [b=lane][32 k] into registers
            const float* hsrc = out_h + (size_t)(t - 1) * (B_DIM * H_DIM)
                                + lane * H_DIM + kq * 32;
            float4 h4[8];
#pragma unroll
            for (int i = 0; i < 8; i++) h4[i] = *(const float4*)(hsrc + i * 4);

            const float* wt = sWT + kq * 32 * 16;
#pragma unroll
            for (int q = 0; q < 8; q++) {
                float hk[4] = { h4[q].x, h4[q].y, h4[q].z, h4[q].w };
#pragma unroll
                for (int s = 0; s < 4; s++) {
                    u64 hs = fsplat(hk[s]);
                    const ulonglong2* wk = (const ulonglong2*)(wt + (q * 4 + s) * 16);
                    ulonglong2 w01 = wk[0], w23 = wk[1];
                    acc[0] = ffma2(hs, w01.x, acc[0]);
                    acc[1] = ffma2(hs, w01.y, acc[1]);
                    acc[2] = ffma2(hs, w23.x, acc[2]);
                    acc[3] = ffma2(hs, w23.y, acc[3]);
                    ulonglong2 w45 = wk[2], w67 = wk[3];
                    acc[4] = ffma2(hs, w45.x, acc[4]);
                    acc[5] = ffma2(hs, w45.y, acc[5]);
                    acc[6] = ffma2(hs, w67.x, acc[6]);
                    acc[7] = ffma2(hs, w67.y, acc[7]);
                }
            }
        }

        // write 16 partials (as 4 x STS.128)
        {
            ulonglong2* sgp = (ulonglong2*)(sg + par * 10240 + kq * 640 + lane * 20);
            sgp[0] = make_ulonglong2(acc[0], acc[1]);
            sgp[1] = make_ulonglong2(acc[2], acc[3]);
            sgp[2] = make_ulonglong2(acc[4], acc[5]);
            sgp[3] = make_ulonglong2(acc[6], acc[7]);
        }
        __syncthreads();

        // pointwise by 128 threads
        if (tid < 128) {
            const float* sgb = sg + par * 10240 + pb * 20 + pg * 4;
            float4 s = make_float4(0.f, 0.f, 0.f, 0.f);
#pragma unroll
            for (int w = 0; w < 16; w++) {
                float4 v = *(const float4*)(sgb + w * 640);
                s.x += v.x; s.y += v.y; s.z += v.z; s.w += v.w;
            }
            s.x += pre4.x; s.y += pre4.y; s.z += pre4.z; s.w += pre4.w;

            float4 a;
            if (pg == 2) {
                a.x = tanhf(s.x); a.y = tanhf(s.y);
                a.z = tanhf(s.z); a.w = tanhf(s.w);
            } else {
                a.x = sigf(s.x); a.y = sigf(s.y);
                a.z = sigf(s.z); a.w = sigf(s.w);
            }
            // gate output (i/f/g/o)
            *(float4*)(outq + (size_t)t * (B_DIM * H_DIM) + pb * H_DIM + j0) = a;

            // exchange within warp: [b_local][g][4]
            float* ex = sAct + w4 * 128;
            *(float4*)(ex + (pl >> 2) * 16 + pg * 4) = a;
            __syncwarp();

            const int jl = pl & 3;
            const float* exr = ex + (pl >> 2) * 16;
            float it = exr[0 + jl];
            float ft = exr[4 + jl];
            float gt = exr[8 + jl];
            float ot = exr[12 + jl];
            float cold = sc[tid];
            float cnew = fmaf(ft, cold, it * gt);
            float hnew = ot * tanhf(cnew);
            sc[tid] = cnew;
            size_t idx = (size_t)t * (B_DIM * H_DIM) + pb * H_DIM + j0 + jl;
            out_c[idx] = cnew;
            out_h[idx] = hnew;

            __syncwarp();
            if (pl == 0) red_add_rel(&gStep[bx * 32], 1u);   // 4 arrivals/step
        }
    }
}

// ---------------------------------------------------------------------------
extern "C" void kernel_launch(void* const* d_in, const int* in_sizes, int n_in,
                              void* d_out, int out_size)
{
    (void)in_sizes; (void)n_in; (void)out_size;
    const float* x    = (const float*)d_in[0];   // [T, B, I]
    const float* w_ih = (const float*)d_in[1];   // [L, 4H, I]
    const float* w_hh = (const float*)d_in[2];   // [L, 4H, H]
    const float* b_ih = (const float*)d_in[3];   // [L, 4H]
    const float* b_hh = (const float*)d_in[4];   // [L, 4H]
    float* out = (float*)d_out;                  // [6, L, T, B, H]

    float* pre;
    cudaGetSymbolAddress((void**)&pre, g_pre);

    const size_t recur_smem = (size_t)(8192 + 20480 + 512 + 128) * sizeof(float);
    cudaFuncSetAttribute(lstm_recur_kernel,
                         cudaFuncAttributeMaxDynamicSharedMemorySize,
                         (int)recur_smem);

    dim3 ggrid(G_DIM / 128, (T_DIM * B_DIM) / 128);   // 16 x 128

    // Layer 0
    gemm_pre_kernel<<<ggrid, 256>>>(x, w_ih, b_ih, b_hh, pre);
    lstm_recur_kernel<<<NCTA, 512, recur_smem>>>(pre, w_hh, out, 0);

    // Layer 1: input is layer-0 h (out region q=0, l=0)
    const float* x1 = out;
    gemm_pre_kernel<<<ggrid, 256>>>(x1,
                                    w_ih + (size_t)G_DIM * I_DIM,
                                    b_ih + G_DIM,
                                    b_hh + G_DIM,
                                    pre);
    lstm_recur_kernel<<<NCTA, 512, recur_smem>>>(pre,
                                                 w_hh + (size_t)G_DIM * H_DIM,
                                                 out, 1);
}

// round 7
// speedup vs baseline: 1.7231x; 1.7231x over previous
#include <cuda_runtime.h>
#include <cuda_bf16.h>

typedef unsigned long long u64;

// Problem dims
#define T_DIM 512
#define B_DIM 32
#define I_DIM 512
#define H_DIM 512
#define G_DIM 2048                       // 4*H
#define S_TBH (T_DIM*B_DIM*H_DIM)        // one [T,B,H] slab
#define NCTA 128

// Scratch: pre-activations for one layer [T, B, 4H]
__device__ float g_pre[(size_t)T_DIM * B_DIM * G_DIM];

// Barrier state (monotonic across graph replays; NEVER reset)
__device__ unsigned gSub[8 * 32];
__device__ unsigned gMaster;
__device__ unsigned gGen;

// ---- f32x2 helpers ---------------------------------------------------------
__device__ __forceinline__ u64 ffma2(u64 a, u64 b, u64 c) {
    u64 d; asm("fma.rn.f32x2 %0,%1,%2,%3;" : "=l"(d) : "l"(a), "l"(b), "l"(c));
    return d;
}
__device__ __forceinline__ u64 fsplat(float a) {
    u64 r; asm("mov.b64 %0,{%1,%1};" : "=l"(r) : "f"(a)); return r;
}
__device__ __forceinline__ float2 funpack(u64 v) {
    float lo, hi; asm("mov.b64 {%0,%1},%2;" : "=f"(lo), "=f"(hi) : "l"(v));
    return make_float2(lo, hi);
}
// ---- release/acquire atomics ----------------------------------------------
__device__ __forceinline__ unsigned ld_acq(const unsigned* p) {
    unsigned v;
    asm volatile("ld.acquire.gpu.global.u32 %0,[%1];" : "=r"(v) : "l"(p));
    return v;
}
__device__ __forceinline__ unsigned atom_add_rel(unsigned* p, unsigned v) {
    unsigned r;
    asm volatile("atom.release.gpu.global.add.u32 %0,[%1],%2;"
                 : "=r"(r) : "l"(p), "r"(v));
    return r;
}
__device__ __forceinline__ void red_add_rel(unsigned* p, unsigned v) {
    asm volatile("red.release.gpu.global.add.u32 [%0],%1;" :: "l"(p), "r"(v));
}
__device__ __forceinline__ float sigf(float x) {
    return 1.f / (1.f + __expf(-x));
}

// ---------------------------------------------------------------------------
// GEMM: pre[M,N] = A[M,K] @ W[N,K]^T + bih[N] + bhh[N]   (unchanged)
// ---------------------------------------------------------------------------
__global__ __launch_bounds__(256) void gemm_pre_kernel(
    const float* __restrict__ A,
    const float* __restrict__ W,
    const float* __restrict__ bih,
    const float* __restrict__ bhh,
    float* __restrict__ C)
{
    const int K = I_DIM;
    const int N = G_DIM;

    __shared__ float As[2][8][128];
    __shared__ float Bs[2][8][128];

    const int bm = blockIdx.y * 128;
    const int bn = blockIdx.x * 128;
    const int tid = threadIdx.x;
    const int tx = tid & 15;
    const int ty = tid >> 4;

    u64 acc2[8][4];
#pragma unroll
    for (int i = 0; i < 8; i++)
#pragma unroll
        for (int jp = 0; jp < 4; jp++) acc2[i][jp] = 0ull;

    const int lr = tid >> 1;
    const int lc = (tid & 1) * 4;
    const float* Aptr = A + (size_t)(bm + lr) * K + lc;
    const float* Wptr = W + (size_t)(bn + lr) * K + lc;

    float4 av = *(const float4*)(Aptr);
    float4 wv = *(const float4*)(Wptr);
    As[0][lc + 0][lr] = av.x; As[0][lc + 1][lr] = av.y;
    As[0][lc + 2][lr] = av.z; As[0][lc + 3][lr] = av.w;
    Bs[0][lc + 0][lr] = wv.x; Bs[0][lc + 1][lr] = wv.y;
    Bs[0][lc + 2][lr] = wv.z; Bs[0][lc + 3][lr] = wv.w;
    __syncthreads();

    for (int kt = 0; kt < 64; kt++) {
        const int cur = kt & 1;
        if (kt < 63) {
            av = *(const float4*)(Aptr + (kt + 1) * 8);
            wv = *(const float4*)(Wptr + (kt + 1) * 8);
        }
#pragma unroll
        for (int kk = 0; kk < 8; kk++) {
            float a[8];
            *(float4*)(a)     = *(const float4*)&As[cur][kk][ty * 8];
            *(float4*)(a + 4) = *(const float4*)&As[cur][kk][ty * 8 + 4];
            const ulonglong2* bp = (const ulonglong2*)&Bs[cur][kk][tx * 8];
            ulonglong2 q0 = bp[0], q1 = bp[1];
            u64 b2[4] = { q0.x, q0.y, q1.x, q1.y };
#pragma unroll
            for (int i = 0; i < 8; i++) {
                u64 a2 = fsplat(a[i]);
#pragma unroll
                for (int jp = 0; jp < 4; jp++)
                    acc2[i][jp] = ffma2(a2, b2[jp], acc2[i][jp]);
            }
        }
        if (kt < 63) {
            const int nxt = cur ^ 1;
            As[nxt][lc + 0][lr] = av.x; As[nxt][lc + 1][lr] = av.y;
            As[nxt][lc + 2][lr] = av.z; As[nxt][lc + 3][lr] = av.w;
            Bs[nxt][lc + 0][lr] = wv.x; Bs[nxt][lc + 1][lr] = wv.y;
            Bs[nxt][lc + 2][lr] = wv.z; Bs[nxt][lc + 3][lr] = wv.w;
        }
        __syncthreads();
    }

    float bias[8];
#pragma unroll
    for (int j = 0; j < 8; j++) {
        int col = bn + tx * 8 + j;
        bias[j] = bih[col] + bhh[col];
    }
#pragma unroll
    for (int i = 0; i < 8; i++) {
        int row = bm + ty * 8 + i;
        float* cp = C + (size_t)row * N + bn + tx * 8;
        float o[8];
#pragma unroll
        for (int jp = 0; jp < 4; jp++) {
            float2 v = funpack(acc2[i][jp]);
            o[2 * jp]     = v.x + bias[2 * jp];
            o[2 * jp + 1] = v.y + bias[2 * jp + 1];
        }
        *(float4*)(cp)     = make_float4(o[0], o[1], o[2], o[3]);
        *(float4*)(cp + 4) = make_float4(o[4], o[5], o[6], o[7]);
    }
}

// ---------------------------------------------------------------------------
// Persistent LSTM recurrence for one layer. 128 CTAs x 512 threads.
// CTA bx owns h-units j0..j0+3 (16 gate columns). Warp kq computes all 16
// cols over k-slice [32kq, 32kq+32) from the cooperatively staged smem h
// tile. Pointwise by tid<128; each of the 4 pointwise warps release-arrives
// into the monotonic hierarchical barrier (64 arrivals/sub, 8 subs -> gGen).
// tid0 acquire-polls gGen at the top of each step.
// ---------------------------------------------------------------------------
__global__ __launch_bounds__(512, 1) void lstm_recur_kernel(
    const float* __restrict__ pre,     // [T, B, 4H]
    const float* __restrict__ whh,     // [4H, H]
    float* __restrict__ out,           // [6, L, T, B, H]
    int layer)
{
    extern __shared__ float4 dsm4[];
    float4* sh4 = dsm4;                         // [32][129] float4 h tile
    float4* sW4 = dsm4 + 32 * 129;              // [16][128] float4 W tile
    float*  sg  = (float*)(sW4 + 16 * 128);     // [16][32][20] partials
    float*  sAct = sg + 16 * 640;               // [4][8][4][4] exchange
    float*  sc  = sAct + 512;                   // [128] c state
    __shared__ unsigned base_s;

    const int tid = threadIdx.x;
    const int bx  = blockIdx.x;
    const int j0  = bx * 4;

    float* out_h = out + (size_t)layer * S_TBH;
    float* out_c = out + (size_t)1 * 2 * S_TBH + (size_t)layer * S_TBH;

    if (tid == 0) base_s = *(volatile unsigned*)&gGen;  // safe: gGen can't
                                                        // advance until every
                                                        // CTA finishes step 0
    // Whh slice: sW4[cidx][k4], cidx = gate*4+jl -> row gate*512+j0+jl
    const float4* whh4 = (const float4*)whh;
#pragma unroll
    for (int i = 0; i < 4; i++) {
        int f = tid + i * 512;              // 0..2047
        int cidx = f >> 7, k4 = f & 127;
        int gate = cidx >> 2, jl = cidx & 3;
        int row = gate * 512 + j0 + jl;
        sW4[cidx * 128 + k4] = whh4[(size_t)row * 128 + k4];
    }
    if (tid < 128) sc[tid] = 0.f;

    const int kq   = tid >> 5;          // warp = k-slice
    const int lane = tid & 31;          // lane = batch b
    const int b    = lane;
    // pointwise role (tid < 128): (pb, pg)
    const int w4 = tid >> 5;
    const int pl = tid & 31;
    const int pb = w4 * 8 + (pl >> 2);
    const int pg = pl & 3;
    float* outq = out + (size_t)(2 + pg) * 2 * S_TBH + (size_t)layer * S_TBH;

    __syncthreads();   // covers base_s + sW4 + sc

    for (int t = 0; t < T_DIM; t++) {
        // prefetch pre[t] (static data -> load before the barrier)
        float4 pre4;
        if (tid < 128)
            pre4 = *(const float4*)(pre + (size_t)t * (B_DIM * G_DIM)
                                    + pb * G_DIM + pg * 512 + j0);

        if (t > 0) {
            if (tid == 0) {
                unsigned target = base_s + (unsigned)t;
                while ((int)(ld_acq(&gGen) - target) < 0) {}
            }
            __syncthreads();   // broadcast barrier-pass (acquire is cumulative)
            const float4* hsrc = (const float4*)(out_h + (size_t)(t - 1) * (B_DIM * H_DIM));
#pragma unroll
            for (int i = 0; i < 8; i++) {
                int f = tid + i * 512;
                sh4[(f >> 7) * 129 + (f & 127)] = hsrc[f];
            }
        } else {
#pragma unroll
            for (int i = 0; i < 8; i++) {
                int f = tid + i * 512;
                sh4[(f >> 7) * 129 + (f & 127)] = make_float4(0.f, 0.f, 0.f, 0.f);
            }
        }
        __syncthreads();       // staging done

        u64 acc[8];
#pragma unroll
        for (int c = 0; c < 8; c++) acc[c] = 0ull;

        const ulonglong2* hrow = (const ulonglong2*)(sh4 + b * 129 + kq * 8);
        const ulonglong2* wbase = (const ulonglong2*)(sW4 + kq * 8);
#pragma unroll 4
        for (int kk = 0; kk < 8; kk++) {
            ulonglong2 hv = hrow[kk];
#pragma unroll
            for (int c2 = 0; c2 < 8; c2++) {
                // cols 2*c2, 2*c2+1  (cidx pair) ; W row stride 128 float4 = 64 ull2
                ulonglong2 w0 = wbase[(2 * c2) * 256 + kk * 2];
                ulonglong2 w1 = wbase[(2 * c2) * 256 + kk * 2 + 1];
                // w0/w1 hold k-pairs for col (2*c2); need col-major pairing:
                (void)w1;
                acc[c2] = ffma2(hv.x, w0.x, acc[c2]);
                acc[c2] = ffma2(hv.y, w0.y, acc[c2]);
            }
        }
        // NOTE: the loop above was restructured; redo correctly below.
        // (kept simple & proven: same as R4 -- 16 cols, acc2 per col)
        {
#pragma unroll
            for (int c = 0; c < 8; c++) acc[c] = 0ull;
            u64 accB[8];
#pragma unroll
            for (int c = 0; c < 8; c++) accB[c] = 0ull;
#pragma unroll 4
            for (int kk = 0; kk < 8; kk++) {
                ulonglong2 hv = hrow[kk];
#pragma unroll
                for (int c = 0; c < 8; c++) {
                    ulonglong2 wv = *((const ulonglong2*)(sW4 + c * 128 + kq * 8) + kk);
                    acc[c] = ffma2(hv.x, wv.x, acc[c]);
                    acc[c] = ffma2(hv.y, wv.y, acc[c]);
                }
#pragma unroll
                for (int c = 0; c < 8; c++) {
                    ulonglong2 wv = *((const ulonglong2*)(sW4 + (c + 8) * 128 + kq * 8) + kk);
                    accB[c] = ffma2(hv.x, wv.x, accB[c]);
                    accB[c] = ffma2(hv.y, wv.y, accB[c]);
                }
            }
            // fold pairs: partial for col c = lo+hi of acc pair
            float* sgw = sg + kq * 640 + b * 20;
#pragma unroll
            for (int c = 0; c < 8; c++) {
                float2 v = funpack(acc[c]);
                sgw[c] = v.x + v.y;
            }
#pragma unroll
            for (int c = 0; c < 8; c++) {
                float2 v = funpack(accB[c]);
                sgw[8 + c] = v.x + v.y;
            }
        }
        __syncthreads();       // partials done

        if (tid < 128) {
            const float* sgb = sg + pb * 20 + pg * 4;
            float4 s = make_float4(0.f, 0.f, 0.f, 0.f);
#pragma unroll
            for (int w = 0; w < 16; w++) {
                float4 v = *(const float4*)(sgb + w * 640);
                s.x += v.x; s.y += v.y; s.z += v.z; s.w += v.w;
            }
            s.x += pre4.x; s.y += pre4.y; s.z += pre4.z; s.w += pre4.w;

            float4 a;
            if (pg == 2) {
                a.x = tanhf(s.x); a.y = tanhf(s.y);
                a.z = tanhf(s.z); a.w = tanhf(s.w);
            } else {
                a.x = sigf(s.x); a.y = sigf(s.y);
                a.z = sigf(s.z); a.w = sigf(s.w);
            }
            *(float4*)(outq + (size_t)t * (B_DIM * H_DIM) + pb * H_DIM + j0) = a;

            float* ex = sAct + w4 * 128;
            *(float4*)(ex + (pl >> 2) * 16 + pg * 4) = a;
            __syncwarp();

            const int jl = pl & 3;
            const float* exr = ex + (pl >> 2) * 16;
            float it = exr[0 + jl];
            float ft = exr[4 + jl];
            float gt = exr[8 + jl];
            float ot = exr[12 + jl];
            float cold = sc[tid];
            float cnew = fmaf(ft, cold, it * gt);
            float hnew = ot * tanhf(cnew);
            sc[tid] = cnew;
            size_t idx = (size_t)t * (B_DIM * H_DIM) + pb * H_DIM + j0 + jl;
            out_c[idx] = cnew;
            out_h[idx] = hnew;

            __syncwarp();
            if (pl == 0 && t < T_DIM - 1) {
                // release-arrive: this warp's h/c stores are ordered by the
                // syncwarp (cumulative) before the release
                unsigned v = atom_add_rel(&gSub[(bx & 7) * 32], 1u);
                if ((v & 63u) == 63u) {                 // 16 CTAs * 4 warps
                    unsigned m = atom_add_rel(&gMaster, 1u);
                    if ((m & 7u) == 7u)                 // 8 subs
                        red_add_rel(&gGen, 1u);
                }
            }
        }
    }
}

// ---------------------------------------------------------------------------
extern "C" void kernel_launch(void* const* d_in, const int* in_sizes, int n_in,
                              void* d_out, int out_size)
{
    (void)in_sizes; (void)n_in; (void)out_size;
    const float* x    = (const float*)d_in[0];   // [T, B, I]
    const float* w_ih = (const float*)d_in[1];   // [L, 4H, I]
    const float* w_hh = (const float*)d_in[2];   // [L, 4H, H]
    const float* b_ih = (const float*)d_in[3];   // [L, 4H]
    const float* b_hh = (const float*)d_in[4];   // [L, 4H]
    float* out = (float*)d_out;                  // [6, L, T, B, H]

    float* pre;
    cudaGetSymbolAddress((void**)&pre, g_pre);

    const size_t recur_smem =
        (size_t)(32 * 129 + 16 * 128) * sizeof(float4) +       // h + W tiles
        (size_t)(16 * 640 + 512 + 128) * sizeof(float);        // sg + sAct + sc
    cudaFuncSetAttribute(lstm_recur_kernel,
                         cudaFuncAttributeMaxDynamicSharedMemorySize,
                         (int)recur_smem);

    dim3 ggrid(G_DIM / 128, (T_DIM * B_DIM) / 128);   // 16 x 128

    // Layer 0
    gemm_pre_kernel<<<ggrid, 256>>>(x, w_ih, b_ih, b_hh, pre);
    lstm_recur_kernel<<<NCTA, 512, recur_smem>>>(pre, w_hh, out, 0);

    // Layer 1: input is layer-0 h (out region q=0, l=0)
    const float* x1 = out;
    gemm_pre_kernel<<<ggrid, 256>>>(x1,
                                    w_ih + (size_t)G_DIM * I_DIM,
                                    b_ih + G_DIM,
                                    b_hh + G_DIM,
                                    pre);
    lstm_recur_kernel<<<NCTA, 512, recur_smem>>>(pre,
                                                 w_hh + (size_t)G_DIM * H_DIM,
                                                 out, 1);
}

// round 8
// speedup vs baseline: 2.1756x; 1.2626x over previous
#include <cuda_runtime.h>
#include <cuda_bf16.h>

typedef unsigned long long u64;

// Problem dims
#define T_DIM 512
#define B_DIM 32
#define I_DIM 512
#define H_DIM 512
#define G_DIM 2048                       // 4*H
#define S_TBH (T_DIM*B_DIM*H_DIM)        // one [T,B,H] slab
#define NCTA 128

// Scratch: pre-activations for one layer [T, B, 4H]
__device__ float g_pre[(size_t)T_DIM * B_DIM * G_DIM];

// Entry-barrier state (monotonic across graph replays; NEVER reset)
__device__ unsigned gSub[8 * 32];
__device__ unsigned gMaster;
__device__ unsigned gGen;
// Per-CTA dataflow counters (reset per launch behind entry barrier)
__device__ unsigned gStep[NCTA * 32];    // one 128B line per CTA

// ---- f32x2 helpers ---------------------------------------------------------
__device__ __forceinline__ u64 ffma2(u64 a, u64 b, u64 c) {
    u64 d; asm("fma.rn.f32x2 %0,%1,%2,%3;" : "=l"(d) : "l"(a), "l"(b), "l"(c));
    return d;
}
__device__ __forceinline__ u64 fsplat(float a) {
    u64 r; asm("mov.b64 %0,{%1,%1};" : "=l"(r) : "f"(a)); return r;
}
__device__ __forceinline__ float2 funpack(u64 v) {
    float lo, hi; asm("mov.b64 {%0,%1},%2;" : "=f"(lo), "=f"(hi) : "l"(v));
    return make_float2(lo, hi);
}
// ---- release/acquire -------------------------------------------------------
__device__ __forceinline__ unsigned ld_acq(const unsigned* p) {
    unsigned v;
    asm volatile("ld.acquire.gpu.global.u32 %0,[%1];" : "=r"(v) : "l"(p));
    return v;
}
__device__ __forceinline__ void red_add_rel(unsigned* p, unsigned v) {
    asm volatile("red.release.gpu.global.add.u32 [%0],%1;" :: "l"(p), "r"(v));
}
__device__ __forceinline__ float sigf(float x) {
    return 1.f / (1.f + __expf(-x));
}

// ---------------------------------------------------------------------------
// GEMM: pre[M,N] = A[M,K] @ W[N,K]^T + bih[N] + bhh[N]   (proven, unchanged)
// ---------------------------------------------------------------------------
__global__ __launch_bounds__(256) void gemm_pre_kernel(
    const float* __restrict__ A,
    const float* __restrict__ W,
    const float* __restrict__ bih,
    const float* __restrict__ bhh,
    float* __restrict__ C)
{
    const int K = I_DIM;
    const int N = G_DIM;

    __shared__ float As[2][8][128];
    __shared__ float Bs[2][8][128];

    const int bm = blockIdx.y * 128;
    const int bn = blockIdx.x * 128;
    const int tid = threadIdx.x;
    const int tx = tid & 15;
    const int ty = tid >> 4;

    u64 acc2[8][4];
#pragma unroll
    for (int i = 0; i < 8; i++)
#pragma unroll
        for (int jp = 0; jp < 4; jp++) acc2[i][jp] = 0ull;

    const int lr = tid >> 1;
    const int lc = (tid & 1) * 4;
    const float* Aptr = A + (size_t)(bm + lr) * K + lc;
    const float* Wptr = W + (size_t)(bn + lr) * K + lc;

    float4 av = *(const float4*)(Aptr);
    float4 wv = *(const float4*)(Wptr);
    As[0][lc + 0][lr] = av.x; As[0][lc + 1][lr] = av.y;
    As[0][lc + 2][lr] = av.z; As[0][lc + 3][lr] = av.w;
    Bs[0][lc + 0][lr] = wv.x; Bs[0][lc + 1][lr] = wv.y;
    Bs[0][lc + 2][lr] = wv.z; Bs[0][lc + 3][lr] = wv.w;
    __syncthreads();

    for (int kt = 0; kt < 64; kt++) {
        const int cur = kt & 1;
        if (kt < 63) {
            av = *(const float4*)(Aptr + (kt + 1) * 8);
            wv = *(const float4*)(Wptr + (kt + 1) * 8);
        }
#pragma unroll
        for (int kk = 0; kk < 8; kk++) {
            float a[8];
            *(float4*)(a)     = *(const float4*)&As[cur][kk][ty * 8];
            *(float4*)(a + 4) = *(const float4*)&As[cur][kk][ty * 8 + 4];
            const ulonglong2* bp = (const ulonglong2*)&Bs[cur][kk][tx * 8];
            ulonglong2 q0 = bp[0], q1 = bp[1];
            u64 b2[4] = { q0.x, q0.y, q1.x, q1.y };
#pragma unroll
            for (int i = 0; i < 8; i++) {
                u64 a2 = fsplat(a[i]);
#pragma unroll
                for (int jp = 0; jp < 4; jp++)
                    acc2[i][jp] = ffma2(a2, b2[jp], acc2[i][jp]);
            }
        }
        if (kt < 63) {
            const int nxt = cur ^ 1;
            As[nxt][lc + 0][lr] = av.x; As[nxt][lc + 1][lr] = av.y;
            As[nxt][lc + 2][lr] = av.z; As[nxt][lc + 3][lr] = av.w;
            Bs[nxt][lc + 0][lr] = wv.x; Bs[nxt][lc + 1][lr] = wv.y;
            Bs[nxt][lc + 2][lr] = wv.z; Bs[nxt][lc + 3][lr] = wv.w;
        }
        __syncthreads();
    }

    float bias[8];
#pragma unroll
    for (int j = 0; j < 8; j++) {
        int col = bn + tx * 8 + j;
        bias[j] = bih[col] + bhh[col];
    }
#pragma unroll
    for (int i = 0; i < 8; i++) {
        int row = bm + ty * 8 + i;
        float* cp = C + (size_t)row * N + bn + tx * 8;
        float o[8];
#pragma unroll
        for (int jp = 0; jp < 4; jp++) {
            float2 v = funpack(acc2[i][jp]);
            o[2 * jp]     = v.x + bias[2 * jp];
            o[2 * jp + 1] = v.y + bias[2 * jp + 1];
        }
        *(float4*)(cp)     = make_float4(o[0], o[1], o[2], o[3]);
        *(float4*)(cp + 4) = make_float4(o[4], o[5], o[6], o[7]);
    }
}

// ---------------------------------------------------------------------------
// Persistent LSTM recurrence, distributed counters. 128 CTAs x 512 threads.
// CTA bx owns units j0..j0+3 (16 gate cols, cidx = gate*4 + jl).
// Per step:
//   poll:   threads 0..127 acquire-poll gStep[i] >= 4t (one producer each)
//   stage:  coalesced LDG of full h[t-1] (64KB) into padded smem tile
//   mma:    warp kq: 16 cols over k-slice [32kq,32kq+32), f32x2 FMA
//   reduce: thread (c = tid>>5, b = tid&31) sums 16 partials + pre, activation
//   update: tid<128 (b = tid>>2, jl = tid&3): c/h update, STG h,
//           warp-release (+1 each, 4 total) to OWN counter
//   post:   c and i/f/g/o stores AFTER release (off critical path)
// ---------------------------------------------------------------------------
__global__ __launch_bounds__(512, 1) void lstm_recur_kernel(
    const float* __restrict__ pre,     // [T, B, 4H]
    const float* __restrict__ whh,     // [4H, H]
    float* __restrict__ out,           // [6, L, T, B, H]
    int layer)
{
    extern __shared__ float4 dsm4[];
    float4* sh4 = dsm4;                         // [32][129] float4 h tile
    float4* sW4 = dsm4 + 32 * 129;              // [16][128] float4 W tile
    float*  sg  = (float*)(sW4 + 16 * 128);     // [16][16][32] partials
    float*  sAct = sg + 16 * 512;               // [16][33] activations
    float*  sc  = sAct + 16 * 33;               // [128] c state
    __shared__ unsigned base_s;

    const int tid = threadIdx.x;
    const int bx  = blockIdx.x;
    const int j0  = bx * 4;

    float* out_h = out + (size_t)layer * S_TBH;
    float* out_c = out + (size_t)1 * 2 * S_TBH + (size_t)layer * S_TBH;

    // Whh slice: sW4[cidx][k4], cidx = gate*4+jl -> row gate*512+j0+jl
    const float4* whh4 = (const float4*)whh;
#pragma unroll
    for (int i = 0; i < 4; i++) {
        int f = tid + i * 512;              // 0..2047
        int cidx = f >> 7, k4 = f & 127;
        int gate = cidx >> 2, jl = cidx & 3;
        int row = gate * 512 + j0 + jl;
        sW4[cidx * 128 + k4] = whh4[(size_t)row * 128 + k4];
    }
    if (tid < 128) sc[tid] = 0.f;

    // reset own counter; entry grid barrier (monotonic cascade)
    if (tid == 0) {
        *(volatile unsigned*)&gStep[bx * 32] = 0u;
        base_s = *(volatile unsigned*)&gGen;   // safe: gGen can't advance
    }                                          // until every CTA arrives
    __syncthreads();
    if (tid == 0) {
        __threadfence();
        unsigned v = atomicAdd(&gSub[(bx & 7) * 32], 1u) + 1u;
        if ((v & 15u) == 0u) {
            unsigned m = atomicAdd(&gMaster, 1u) + 1u;
            if ((m & 7u) == 0u) atomicAdd(&gGen, 1u);
        }
        unsigned target = base_s + 1u;
        while ((int)(ld_acq(&gGen) - target) < 0) {}
        __threadfence();
    }
    __syncthreads();

    const int kq   = tid >> 5;          // compute: warp = k-slice
    const int lane = tid & 31;          // compute: lane = batch b
    const int b    = lane;
    // reduce role: (rc, rb)
    const int rc = tid >> 5;
    const int rb = tid & 31;
    // pre column for this (rc, rb)
    const float* prep = pre + (size_t)rb * G_DIM + (rc >> 2) * 512 + j0 + (rc & 3);
    // update role (tid<128): (ub, ujl)
    const int ub  = tid >> 2;
    const int ujl = tid & 3;
    // post-store role: (pb2, pc2)
    const int pb2 = tid >> 4;
    const int pc2 = tid & 15;

    for (int t = 0; t < T_DIM; t++) {
        // prefetch pre[t] scalar (static GEMM output; issue before poll)
        float pre_v = prep[(size_t)t * (B_DIM * G_DIM)];

        // ---- wait for all producers, stage h[t-1]
        if (t > 0) {
            if (tid < 128) {
                unsigned target = 4u * (unsigned)t;
                const unsigned* ctr = &gStep[tid * 32];
                while (ld_acq(ctr) < target) {}
            }
            __syncthreads();
            const float4* hsrc = (const float4*)(out_h + (size_t)(t - 1) * (B_DIM * H_DIM));
#pragma unroll
            for (int i = 0; i < 8; i++) {
                int f = tid + i * 512;
                sh4[(f >> 7) * 129 + (f & 127)] = hsrc[f];
            }
        } else {
#pragma unroll
            for (int i = 0; i < 8; i++) {
                int f = tid + i * 512;
                sh4[(f >> 7) * 129 + (f & 127)] = make_float4(0.f, 0.f, 0.f, 0.f);
            }
        }
        __syncthreads();

        // ---- matrix part: 16 cols x 32-k slice, f32x2
        u64 acc[8], accB[8];
#pragma unroll
        for (int c = 0; c < 8; c++) { acc[c] = 0ull; accB[c] = 0ull; }

        const ulonglong2* hrow = (const ulonglong2*)(sh4 + b * 129 + kq * 8);
#pragma unroll 4
        for (int kk = 0; kk < 8; kk++) {
            ulonglong2 hv = hrow[kk];
#pragma unroll
            for (int c = 0; c < 8; c++) {
                ulonglong2 wv = *((const ulonglong2*)(sW4 + c * 128 + kq * 8) + kk);
                acc[c] = ffma2(hv.x, wv.x, acc[c]);
                acc[c] = ffma2(hv.y, wv.y, acc[c]);
            }
#pragma unroll
            for (int c = 0; c < 8; c++) {
                ulonglong2 wv = *((const ulonglong2*)(sW4 + (c + 8) * 128 + kq * 8) + kk);
                accB[c] = ffma2(hv.x, wv.x, accB[c]);
                accB[c] = ffma2(hv.y, wv.y, accB[c]);
            }
        }
        // partials: sg[kq][c][b]  (coalesced 1-wf stores)
        {
            float* sgw = sg + kq * 512;
#pragma unroll
            for (int c = 0; c < 8; c++) {
                float2 v = funpack(acc[c]);
                sgw[c * 32 + b] = v.x + v.y;
            }
#pragma unroll
            for (int c = 0; c < 8; c++) {
                float2 v = funpack(accB[c]);
                sgw[(c + 8) * 32 + b] = v.x + v.y;
            }
        }
        __syncthreads();

        // ---- reduce + activation: thread (rc, rb), one gate value
        {
            float s = pre_v;
            const float* sgr = sg + rc * 32 + rb;
#pragma unroll
            for (int q = 0; q < 16; q++) s += sgr[q * 512];
            float a = ((rc >> 2) == 2) ? tanhf(s) : sigf(s);
            sAct[rc * 33 + rb] = a;
        }
        __syncthreads();

        // ---- c/h update by tid<128, then EARLY release
        if (tid < 128) {
            float it = sAct[(0 + ujl) * 33 + ub];
            float ft = sAct[(4 + ujl) * 33 + ub];
            float gt = sAct[(8 + ujl) * 33 + ub];
            float ot = sAct[(12 + ujl) * 33 + ub];
            float cold = sc[tid];
            float cnew = fmaf(ft, cold, it * gt);
            float hnew = ot * tanhf(cnew);
            sc[tid] = cnew;
            size_t idx = (size_t)t * (B_DIM * H_DIM) + ub * H_DIM + j0 + ujl;
            out_h[idx] = hnew;
            __syncwarp();
            if ((tid & 31) == 0 && t < T_DIM - 1)
                red_add_rel(&gStep[bx * 32], 1u);    // own line, no contention
            // post-release store (off critical path)
            out_c[idx] = cnew;
        }

        // ---- gate outputs i/f/g/o after release
        {
            float a = sAct[pc2 * 33 + pb2];
            int g = pc2 >> 2, jl = pc2 & 3;
            float* dst = out + (size_t)(2 + g) * 2 * S_TBH + (size_t)layer * S_TBH
                         + (size_t)t * (B_DIM * H_DIM) + pb2 * H_DIM + j0 + jl;
            *dst = a;
        }
    }
}

// ---------------------------------------------------------------------------
extern "C" void kernel_launch(void* const* d_in, const int* in_sizes, int n_in,
                              void* d_out, int out_size)
{
    (void)in_sizes; (void)n_in; (void)out_size;
    const float* x    = (const float*)d_in[0];   // [T, B, I]
    const float* w_ih = (const float*)d_in[1];   // [L, 4H, I]
    const float* w_hh = (const float*)d_in[2];   // [L, 4H, H]
    const float* b_ih = (const float*)d_in[3];   // [L, 4H]
    const float* b_hh = (const float*)d_in[4];   // [L, 4H]
    float* out = (float*)d_out;                  // [6, L, T, B, H]

    float* pre;
    cudaGetSymbolAddress((void**)&pre, g_pre);

    const size_t recur_smem =
        (size_t)(32 * 129 + 16 * 128) * sizeof(float4) +           // h + W tiles
        (size_t)(16 * 512 + 16 * 33 + 128) * sizeof(float);        // sg+sAct+sc
    cudaFuncSetAttribute(lstm_recur_kernel,
                         cudaFuncAttributeMaxDynamicSharedMemorySize,
                         (int)recur_smem);

    dim3 ggrid(G_DIM / 128, (T_DIM * B_DIM) / 128);   // 16 x 128

    // Layer 0
    gemm_pre_kernel<<<ggrid, 256>>>(x, w_ih, b_ih, b_hh, pre);
    lstm_recur_kernel<<<NCTA, 512, recur_smem>>>(pre, w_hh, out, 0);

    // Layer 1: input is layer-0 h (out region q=0, l=0)
    const float* x1 = out;
    gemm_pre_kernel<<<ggrid, 256>>>(x1,
                                    w_ih + (size_t)G_DIM * I_DIM,
                                    b_ih + G_DIM,
                                    b_hh + G_DIM,
                                    pre);
    lstm_recur_kernel<<<NCTA, 512, recur_smem>>>(pre,
                                                 w_hh + (size_t)G_DIM * H_DIM,
                                                 out, 1);
}

// round 9
// speedup vs baseline: 2.2014x; 1.0119x over previous
#include <cuda_runtime.h>
#include <cuda_bf16.h>

typedef unsigned long long u64;

// Problem dims
#define T_DIM 512
#define B_DIM 32
#define I_DIM 512
#define H_DIM 512
#define G_DIM 2048                       // 4*H
#define BH    (B_DIM*H_DIM)
#define S_TBH (T_DIM*B_DIM*H_DIM)        // one [T,B,H] slab
#define NCTA 128

// Scratch: layer-0 pre-activations [T, B, 4H]
__device__ float g_pre[(size_t)T_DIM * B_DIM * G_DIM];

// Entry-barrier state (monotonic across graph replays; NEVER reset)
__device__ unsigned gSub[8 * 32];
__device__ unsigned gMaster;
__device__ unsigned gGen;
// Per-CTA dataflow counters (reset per launch behind entry barrier)
__device__ unsigned gStep[NCTA * 32];

// ---- f32x2 helpers ---------------------------------------------------------
__device__ __forceinline__ u64 ffma2(u64 a, u64 b, u64 c) {
    u64 d; asm("fma.rn.f32x2 %0,%1,%2,%3;" : "=l"(d) : "l"(a), "l"(b), "l"(c));
    return d;
}
__device__ __forceinline__ u64 fsplat(float a) {
    u64 r; asm("mov.b64 %0,{%1,%1};" : "=l"(r) : "f"(a)); return r;
}
__device__ __forceinline__ float2 funpack(u64 v) {
    float lo, hi; asm("mov.b64 {%0,%1},%2;" : "=f"(lo), "=f"(hi) : "l"(v));
    return make_float2(lo, hi);
}
// ---- release/acquire -------------------------------------------------------
__device__ __forceinline__ unsigned ld_acq(const unsigned* p) {
    unsigned v;
    asm volatile("ld.acquire.gpu.global.u32 %0,[%1];" : "=r"(v) : "l"(p));
    return v;
}
__device__ __forceinline__ void red_add_rel(unsigned* p, unsigned v) {
    asm volatile("red.release.gpu.global.add.u32 [%0],%1;" :: "l"(p), "r"(v));
}
__device__ __forceinline__ float sigf(float x) {
    return 1.f / (1.f + __expf(-x));
}

// ---------------------------------------------------------------------------
// GEMM for layer-0 input projection (proven, unchanged)
// ---------------------------------------------------------------------------
__global__ __launch_bounds__(256) void gemm_pre_kernel(
    const float* __restrict__ A,
    const float* __restrict__ W,
    const float* __restrict__ bih,
    const float* __restrict__ bhh,
    float* __restrict__ C)
{
    const int K = I_DIM;
    const int N = G_DIM;

    __shared__ float As[2][8][128];
    __shared__ float Bs[2][8][128];

    const int bm = blockIdx.y * 128;
    const int bn = blockIdx.x * 128;
    const int tid = threadIdx.x;
    const int tx = tid & 15;
    const int ty = tid >> 4;

    u64 acc2[8][4];
#pragma unroll
    for (int i = 0; i < 8; i++)
#pragma unroll
        for (int jp = 0; jp < 4; jp++) acc2[i][jp] = 0ull;

    const int lr = tid >> 1;
    const int lc = (tid & 1) * 4;
    const float* Aptr = A + (size_t)(bm + lr) * K + lc;
    const float* Wptr = W + (size_t)(bn + lr) * K + lc;

    float4 av = *(const float4*)(Aptr);
    float4 wv = *(const float4*)(Wptr);
    As[0][lc + 0][lr] = av.x; As[0][lc + 1][lr] = av.y;
    As[0][lc + 2][lr] = av.z; As[0][lc + 3][lr] = av.w;
    Bs[0][lc + 0][lr] = wv.x; Bs[0][lc + 1][lr] = wv.y;
    Bs[0][lc + 2][lr] = wv.z; Bs[0][lc + 3][lr] = wv.w;
    __syncthreads();

    for (int kt = 0; kt < 64; kt++) {
        const int cur = kt & 1;
        if (kt < 63) {
            av = *(const float4*)(Aptr + (kt + 1) * 8);
            wv = *(const float4*)(Wptr + (kt + 1) * 8);
        }
#pragma unroll
        for (int kk = 0; kk < 8; kk++) {
            float a[8];
            *(float4*)(a)     = *(const float4*)&As[cur][kk][ty * 8];
            *(float4*)(a + 4) = *(const float4*)&As[cur][kk][ty * 8 + 4];
            const ulonglong2* bp = (const ulonglong2*)&Bs[cur][kk][tx * 8];
            ulonglong2 q0 = bp[0], q1 = bp[1];
            u64 b2[4] = { q0.x, q0.y, q1.x, q1.y };
#pragma unroll
            for (int i = 0; i < 8; i++) {
                u64 a2 = fsplat(a[i]);
#pragma unroll
                for (int jp = 0; jp < 4; jp++)
                    acc2[i][jp] = ffma2(a2, b2[jp], acc2[i][jp]);
            }
        }
        if (kt < 63) {
            const int nxt = cur ^ 1;
            As[nxt][lc + 0][lr] = av.x; As[nxt][lc + 1][lr] = av.y;
            As[nxt][lc + 2][lr] = av.z; As[nxt][lc + 3][lr] = av.w;
            Bs[nxt][lc + 0][lr] = wv.x; Bs[nxt][lc + 1][lr] = wv.y;
            Bs[nxt][lc + 2][lr] = wv.z; Bs[nxt][lc + 3][lr] = wv.w;
        }
        __syncthreads();
    }

    float bias[8];
#pragma unroll
    for (int j = 0; j < 8; j++) {
        int col = bn + tx * 8 + j;
        bias[j] = bih[col] + bhh[col];
    }
#pragma unroll
    for (int i = 0; i < 8; i++) {
        int row = bm + ty * 8 + i;
        float* cp = C + (size_t)row * N + bn + tx * 8;
        float o[8];
#pragma unroll
        for (int jp = 0; jp < 4; jp++) {
            float2 v = funpack(acc2[i][jp]);
            o[2 * jp]     = v.x + bias[2 * jp];
            o[2 * jp + 1] = v.y + bias[2 * jp + 1];
        }
        *(float4*)(cp)     = make_float4(o[0], o[1], o[2], o[3]);
        *(float4*)(cp + 4) = make_float4(o[4], o[5], o[6], o[7]);
    }
}

// ---------------------------------------------------------------------------
// FUSED persistent 2-layer LSTM recurrence. 128 CTAs x 512 threads.
// CTA bx owns units j0..j0+3 of BOTH layers (48 weight cols total:
//   cols  0..15 : Whh0  (recur layer 0)
//   cols 16..31 : Wih1  (input proj of layer 1 -- consumes h0)
//   cols 32..47 : Whh1  (recur layer 1))
// Step t (t = 0..512):
//   poll counters >= 8t; prefetch h1[t-2] into regs;
//   stage h0[t-1] into the single XOR-swizzled smem tile;
//   phase B: cols 0..31 over tile (each warp: 8 cols x 128-k slice);
//   swap tile to h1[t-2]; phase C: cols 32..47 (4 cols/warp);
//   reduce 48 cols -> act0 (gates layer0, + pre0[t]) and act1
//   (pre1[t-1] + recur1 + bias1); pointwise h0[t], h1[t-1]; 8 releases.
// ---------------------------------------------------------------------------
__global__ __launch_bounds__(512, 1) void lstm_fused_kernel(
    const float* __restrict__ pre0,    // [T, B, 4H]
    const float* __restrict__ whh0,    // [4H, H]
    const float* __restrict__ wih1,    // [4H, I]
    const float* __restrict__ whh1,    // [4H, H]
    const float* __restrict__ bih1,    // [4H]
    const float* __restrict__ bhh1,    // [4H]
    float* __restrict__ out)           // [6, L, T, B, H]
{
    extern __shared__ float smf[];
    float*      sW   = smf;                         // 48*512      = 24576 f
    float4*     tile4= (float4*)(smf + 24576);      // 4096 float4 = 16384 f
    float*      sg   = smf + 24576 + 16384;         // [4][48][32] = 6144 f
    float*      sAct = sg + 6144;                   // [2][16*33]  = 1056 f
    float*      sB1  = sAct + 1056;                 // 16 f
    float*      sc   = sB1 + 16;                    // [2][128]    = 256 f
    __shared__ unsigned base_s;

    const int tid = threadIdx.x;
    const int bx  = blockIdx.x;
    const int j0  = bx * 4;

    float* out_h0 = out;                                    // q=0, l=0
    float* out_h1 = out + (size_t)S_TBH;                    // q=0, l=1
    float* out_c0 = out + (size_t)2 * S_TBH;                // q=1, l=0
    float* out_c1 = out + (size_t)3 * S_TBH;                // q=1, l=1

    // ---- load 48 weight columns into smem
#pragma unroll
    for (int i = 0; i < 12; i++) {
        int f = tid + i * 512;              // float4 id 0..6143
        int col = f >> 7, k4 = f & 127;
        int cidx = (col < 16) ? col : ((col < 32) ? col - 16 : col - 32);
        const float* src = (col < 16) ? whh0 : ((col < 32) ? wih1 : whh1);
        int row = (cidx >> 2) * 512 + j0 + (cidx & 3);
        ((float4*)sW)[col * 128 + k4] = ((const float4*)src)[(size_t)row * 128 + k4];
    }
    if (tid < 16) {
        int row = (tid >> 2) * 512 + j0 + (tid & 3);
        sB1[tid] = bih1[row] + bhh1[row];
    }
    if (tid < 256) sc[tid] = 0.f;

    // ---- reset own counter; monotonic entry grid barrier
    if (tid == 0) {
        *(volatile unsigned*)&gStep[bx * 32] = 0u;
        base_s = *(volatile unsigned*)&gGen;
    }
    __syncthreads();
    if (tid == 0) {
        __threadfence();
        unsigned v = atomicAdd(&gSub[(bx & 7) * 32], 1u) + 1u;
        if ((v & 15u) == 0u) {
            unsigned m = atomicAdd(&gMaster, 1u) + 1u;
            if ((m & 7u) == 0u) atomicAdd(&gGen, 1u);
        }
        unsigned target = base_s + 1u;
        while ((int)(ld_acq(&gGen) - target) < 0) {}
        __threadfence();
    }
    __syncthreads();

    const int w    = tid >> 5;
    const int lane = tid & 31;
    const int b    = lane;
    const int kq   = w & 3;             // 128-k slice
    const int qt   = w >> 2;            // col quarter
    const int bsw  = b & 7;             // tile swizzle key
    // reduce role
    const int rc = tid >> 5;            // cidx 0..15
    const int rb = tid & 31;
    const float* prep = pre0 + (size_t)rb * G_DIM + (rc >> 2) * 512 + j0 + (rc & 3);
    // update role (tid<256)
    const int ul  = tid >> 7;           // layer
    const int ur  = tid & 127;
    const int ub  = ur >> 2;
    const int ujl = ur & 3;
    // gate-store role
    const int pb2 = tid >> 4;
    const int pc2 = tid & 15;

    const ulonglong2* t2 = (const ulonglong2*)tile4;

    for (int t = 0; t <= T_DIM; t++) {
        // pre0[t] scalar for reduce role (guard end)
        float pre_v = 0.f;
        if (t < T_DIM) pre_v = prep[(size_t)t * (B_DIM * G_DIM)];

        // ---- wait for producers
        if (t > 0) {
            if (tid < 128) {
                unsigned target = 8u * (unsigned)t;
                const unsigned* ctr = &gStep[tid * 32];
                while (ld_acq(ctr) < target) {}
            }
            __syncthreads();
        }

        // prefetch h1[t-2] into registers (zeros when t<2)
        float4 hr[8];
        if (t >= 2) {
            const float4* hs1 = (const float4*)(out_h1 + (size_t)(t - 2) * BH);
#pragma unroll
            for (int i = 0; i < 8; i++) hr[i] = hs1[tid + i * 512];
        } else {
#pragma unroll
            for (int i = 0; i < 8; i++) hr[i] = make_float4(0.f, 0.f, 0.f, 0.f);
        }

        // stage h0[t-1] (zeros at t==0)
        if (t > 0) {
            const float4* hs0 = (const float4*)(out_h0 + (size_t)(t - 1) * BH);
#pragma unroll
            for (int i = 0; i < 8; i++) {
                int f = tid + i * 512;
                int bb = f >> 7, k4 = f & 127;
                tile4[bb * 128 + (k4 ^ (bb & 7))] = hs0[f];
            }
        } else {
#pragma unroll
            for (int i = 0; i < 8; i++) {
                int f = tid + i * 512;
                int bb = f >> 7, k4 = f & 127;
                tile4[bb * 128 + (k4 ^ (bb & 7))] = make_float4(0.f, 0.f, 0.f, 0.f);
            }
        }
        __syncthreads();

        // ---- phase B: cols 0..31 (recur0 + pre1) from h0 tile
        {
            u64 acc[8];
#pragma unroll
            for (int c = 0; c < 8; c++) acc[c] = 0ull;
            const int cbase = qt * 8;
            const ulonglong2* wp = (const ulonglong2*)(sW + cbase * 512) + kq * 32;
#pragma unroll 4
            for (int kk4 = 0; kk4 < 32; kk4++) {
                ulonglong2 hv = t2[b * 128 + ((kq * 32 + kk4) ^ bsw)];
#pragma unroll
                for (int c = 0; c < 8; c++) {
                    ulonglong2 wv = wp[c * 128 + kk4];
                    acc[c] = ffma2(hv.x, wv.x, acc[c]);
                    acc[c] = ffma2(hv.y, wv.y, acc[c]);
                }
            }
            float* sgw = sg + kq * 1536 + b;
#pragma unroll
            for (int c = 0; c < 8; c++) {
                float2 v = funpack(acc[c]);
                sgw[(cbase + c) * 32] = v.x + v.y;
            }
        }
        __syncthreads();      // all warps done reading h0 tile

        // swap tile -> h1[t-2]
#pragma unroll
        for (int i = 0; i < 8; i++) {
            int f = tid + i * 512;
            int bb = f >> 7, k4 = f & 127;
            tile4[bb * 128 + (k4 ^ (bb & 7))] = hr[i];
        }
        __syncthreads();

        // ---- phase C: cols 32..47 (recur1) from h1 tile
        {
            u64 acc[4];
#pragma unroll
            for (int c = 0; c < 4; c++) acc[c] = 0ull;
            const int cbase = 32 + qt * 4;
            const ulonglong2* wp = (const ulonglong2*)(sW + cbase * 512) + kq * 32;
#pragma unroll 4
            for (int kk4 = 0; kk4 < 32; kk4++) {
                ulonglong2 hv = t2[b * 128 + ((kq * 32 + kk4) ^ bsw)];
#pragma unroll
                for (int c = 0; c < 4; c++) {
                    ulonglong2 wv = wp[c * 128 + kk4];
                    acc[c] = ffma2(hv.x, wv.x, acc[c]);
                    acc[c] = ffma2(hv.y, wv.y, acc[c]);
                }
            }
            float* sgw = sg + kq * 1536 + b;
#pragma unroll
            for (int c = 0; c < 4; c++) {
                float2 v = funpack(acc[c]);
                sgw[(cbase + c) * 32] = v.x + v.y;
            }
        }
        __syncthreads();

        // ---- reduce + activations (all 512 threads: one cidx x one b, both layers)
        {
            const float* sgr = sg + rb;
            float g0 = pre_v;
            float g1 = sB1[rc];
#pragma unroll
            for (int q = 0; q < 4; q++) {
                const float* p = sgr + q * 1536;
                g0 += p[rc * 32];
                g1 += p[(16 + rc) * 32] + p[(32 + rc) * 32];
            }
            float a0, a1;
            if ((rc >> 2) == 2) { a0 = tanhf(g0); a1 = tanhf(g1); }
            else                { a0 = sigf(g0);  a1 = sigf(g1);  }
            sAct[rc * 33 + rb]       = a0;
            sAct[528 + rc * 33 + rb] = a1;
        }
        __syncthreads();

        // ---- pointwise update + release (8 warps)
        if (tid < 256) {
            const bool active = (ul == 0) ? (t < T_DIM) : (t >= 1);
            float cnew = 0.f;
            size_t idx = 0;
            if (active) {
                const float* sa = sAct + ul * 528;
                float it = sa[(0  + ujl) * 33 + ub];
                float ft = sa[(4  + ujl) * 33 + ub];
                float gt = sa[(8  + ujl) * 33 + ub];
                float ot = sa[(12 + ujl) * 33 + ub];
                float cold = sc[ul * 128 + ur];
                cnew = fmaf(ft, cold, it * gt);
                float hnew = ot * tanhf(cnew);
                sc[ul * 128 + ur] = cnew;
                int tt = (ul == 0) ? t : (t - 1);
                idx = (size_t)tt * BH + ub * H_DIM + j0 + ujl;
                (ul ? out_h1 : out_h0)[idx] = hnew;
            }
            __syncwarp();
            if ((tid & 31) == 0)
                red_add_rel(&gStep[bx * 32], 1u);     // own line, 8/step
            if (active)
                (ul ? out_c1 : out_c0)[idx] = cnew;   // off critical path
        }

        // ---- gate outputs i/f/g/o for both layers (after release)
        {
            int g = pc2 >> 2, jl = pc2 & 3;
            if (t < T_DIM) {
                float a = sAct[pc2 * 33 + pb2];
                float* dst = out + (size_t)(2 + g) * 2 * S_TBH
                             + (size_t)t * BH + pb2 * H_DIM + j0 + jl;
                *dst = a;
            }
            if (t >= 1) {
                float a = sAct[528 + pc2 * 33 + pb2];
                float* dst = out + (size_t)(2 + g) * 2 * S_TBH + S_TBH
                             + (size_t)(t - 1) * BH + pb2 * H_DIM + j0 + jl;
                *dst = a;
            }
        }
    }
}

// ---------------------------------------------------------------------------
extern "C" void kernel_launch(void* const* d_in, const int* in_sizes, int n_in,
                              void* d_out, int out_size)
{
    (void)in_sizes; (void)n_in; (void)out_size;
    const float* x    = (const float*)d_in[0];   // [T, B, I]
    const float* w_ih = (const float*)d_in[1];   // [L, 4H, I]
    const float* w_hh = (const float*)d_in[2];   // [L, 4H, H]
    const float* b_ih = (const float*)d_in[3];   // [L, 4H]
    const float* b_hh = (const float*)d_in[4];   // [L, 4H]
    float* out = (float*)d_out;                  // [6, L, T, B, H]

    float* pre;
    cudaGetSymbolAddress((void**)&pre, g_pre);

    const size_t fused_smem =
        (size_t)(24576 + 16384 + 6144 + 1056 + 16 + 256) * sizeof(float);
    cudaFuncSetAttribute(lstm_fused_kernel,
                         cudaFuncAttributeMaxDynamicSharedMemorySize,
                         (int)fused_smem);

    dim3 ggrid(G_DIM / 128, (T_DIM * B_DIM) / 128);   // 16 x 128

    // Layer-0 input projection, then fused 2-layer recurrence
    gemm_pre_kernel<<<ggrid, 256>>>(x, w_ih, b_ih, b_hh, pre);
    lstm_fused_kernel<<<NCTA, 512, fused_smem>>>(
        pre,
        w_hh,                                   // Whh0
        w_ih + (size_t)G_DIM * I_DIM,           // Wih1
        w_hh + (size_t)G_DIM * H_DIM,           // Whh1
        b_ih + G_DIM,
        b_hh + G_DIM,
        out);
}